// round 13
// baseline (speedup 1.0000x reference)
#include <cuda_runtime.h>
#include <math.h>
#include <stdint.h>

// ---------------- problem constants ----------------
#define BB      4
#define CIN     23
#define TT      8
#define HH      128
#define WW      128
#define DM      256
#define DSTATE  16
#define DCONV   4
#define DINNER  512
#define HEADDIM 64
#define NHEADS  8
#define CONVDIM 544
#define DPROJ   1064
#define HP      32
#define WP      32
#define LL      8192
#define MTOK    32768
#define KPATCH  368
#define QCHUNK  64
#define NCHUNK  128
#define NOUT    (BB*CIN*TT*HH*WW)

// ---------------- scratch ----------------
__device__ __align__(128) float g_patchWT[KPATCH * DM];
__device__ __align__(128) float g_Win_r [DM * DPROJ];
__device__ __align__(128) float g_Wout_r[DINNER * DM];
__device__ __align__(128) float g_Wun_r [DM * KPATCH];
__device__ __align__(128) float g_Wcomb [DINNER * KPATCH];    // W_out @ W_un (tf32)
__device__ __align__(128) float g_xs    [MTOK * DM];
__device__ __align__(128) float g_zx    [MTOK * DPROJ];
__device__ __align__(128) float g_xBCs  [MTOK * CONVDIM];
__device__ __align__(128) float g_dAdt  [MTOK * NHEADS * 2];   // (dA, dt) pairs
__device__ __align__(128) float g_S     [BB*NCHUNK*NHEADS*HEADDIM*DSTATE];
__device__ __align__(128) float g_P     [BB*NCHUNK*NHEADS];
__device__ __align__(128) float g_hinit [BB*NCHUNK*NHEADS*HEADDIM*DSTATE];
__device__ __align__(128) float g_ynorm [MTOK * DINNER];

// ---------------- helpers ---------------------------------------------------
__device__ __forceinline__ uint32_t f2tf(float f) {
    uint32_t u;
    asm("cvt.rna.tf32.f32 %0, %1;" : "=r"(u) : "f"(f));
    return u;
}
__device__ __forceinline__ float f2tf_f(float f) { return __uint_as_float(f2tf(f)); }

__device__ __forceinline__ void mma8(float* c, const uint32_t* a, const uint32_t* b) {
    asm volatile(
        "mma.sync.aligned.m16n8k8.row.col.f32.tf32.tf32.f32 "
        "{%0,%1,%2,%3},{%4,%5,%6,%7},{%8,%9},{%0,%1,%2,%3};"
        : "+f"(c[0]), "+f"(c[1]), "+f"(c[2]), "+f"(c[3])
        : "r"(a[0]), "r"(a[1]), "r"(a[2]), "r"(a[3]), "r"(b[0]), "r"(b[1]));
}
__device__ __forceinline__ void ldsm4(uint32_t* r, uint32_t addr) {
    asm volatile("ldmatrix.sync.aligned.m8n8.x4.shared.b16 {%0,%1,%2,%3},[%4];"
                 : "=r"(r[0]), "=r"(r[1]), "=r"(r[2]), "=r"(r[3]) : "r"(addr));
}
__device__ __forceinline__ void cpasync16(uint32_t saddr, const void* gaddr) {
    asm volatile("cp.async.cg.shared.global [%0], [%1], 16;\n" :: "r"(saddr), "l"(gaddr));
}
__device__ __forceinline__ void cpasync16z(uint32_t saddr, const void* gaddr, int sz) {
    asm volatile("cp.async.cg.shared.global [%0], [%1], 16, %2;\n"
                 :: "r"(saddr), "l"(gaddr), "r"(sz));
}
#define CP_COMMIT() asm volatile("cp.async.commit_group;\n" ::: "memory")
#define CP_WAIT2()  asm volatile("cp.async.wait_group 2;\n" ::: "memory")

#define ASTG 2560   // 128*20
#define BSTG 2176   // 16*136
#define GEMM_SMEM ((4*ASTG + 4*BSTG) * 4)

// ---------------- generic cp.async TF32 GEMM (inputs pre-rounded) ----------
__global__ __launch_bounds__(256, 2) void gemm_cp(
    const float* __restrict__ A, const float* __restrict__ B,
    float* __restrict__ C, int M, int N, int K, int roundOut)
{
    extern __shared__ uint32_t sm[];
    const uint32_t smb = (uint32_t)__cvta_generic_to_shared(sm);
    const int tid = threadIdx.x, warp = tid >> 5, lane = tid & 31;
    const int warpM = warp >> 2, warpN = warp & 3;
    const int g = lane >> 2, t4 = lane & 3;
    const int bm = blockIdx.y * 128, bn = blockIdx.x * 128;
    const int aRow = tid >> 2, aK = (tid & 3) * 4;
    const int bK = tid >> 5, bCol = (tid & 31) * 4;
    const int bsz = (bn + bCol) < N ? 16 : 0;
    const int T = K >> 4;

    float acc[4][4][4];
#pragma unroll
    for (int i = 0; i < 4; i++)
#pragma unroll
        for (int j = 0; j < 4; j++)
#pragma unroll
            for (int q = 0; q < 4; q++) acc[i][j][q] = 0.f;

#define ISSUE(t) { \
    int s_ = (t) & 3; int k0_ = (t) << 4; \
    uint32_t sa_ = smb + s_ * (ASTG * 4); \
    uint32_t sb_ = smb + (4 * ASTG * 4) + s_ * (BSTG * 4); \
    cpasync16(sa_ + (aRow * 20 + aK) * 4, &A[(size_t)(bm + aRow) * K + k0_ + aK]); \
    cpasync16(sa_ + ((aRow + 64) * 20 + aK) * 4, &A[(size_t)(bm + aRow + 64) * K + k0_ + aK]); \
    cpasync16z(sb_ + (bK * 136 + bCol) * 4, &B[(size_t)(k0_ + bK) * N + bn + bCol], bsz); \
    cpasync16z(sb_ + ((bK + 8) * 136 + bCol) * 4, &B[(size_t)(k0_ + bK + 8) * N + bn + bCol], bsz); }

    ISSUE(0); CP_COMMIT();
    ISSUE(1); CP_COMMIT();
    ISSUE(2); CP_COMMIT();
    CP_WAIT2();
    __syncthreads();

    for (int t = 0; t < T; t++) {
        const int s = t & 3;
        const uint32_t sa = smb + s * (ASTG * 4);
        const uint32_t* Bs = sm + 4 * ASTG + s * BSTG;
#pragma unroll
        for (int kk = 0; kk < 16; kk += 8) {
            uint32_t af[4][4], bf[4][2];
#pragma unroll
            for (int i = 0; i < 4; i++) {
                const int m0 = warpM * 64 + i * 16;
                ldsm4(af[i], sa + ((m0 + (lane & 15)) * 20 + kk + ((lane & 16) >> 2)) * 4);
            }
#pragma unroll
            for (int j = 0; j < 4; j++) {
                const int n0 = warpN * 32 + j * 8;
                bf[j][0] = Bs[(kk + t4) * 136 + n0 + g];
                bf[j][1] = Bs[(kk + t4 + 4) * 136 + n0 + g];
            }
#pragma unroll
            for (int i = 0; i < 4; i++)
#pragma unroll
                for (int j = 0; j < 4; j++)
                    mma8(acc[i][j], af[i], bf[j]);
        }
        if (t + 3 < T) ISSUE(t + 3);
        CP_COMMIT();
        CP_WAIT2();
        __syncthreads();
    }
#undef ISSUE

#pragma unroll
    for (int i = 0; i < 4; i++) {
        const int r0 = bm + warpM * 64 + i * 16 + g;
#pragma unroll
        for (int j = 0; j < 4; j++) {
            const int c0 = bn + warpN * 32 + j * 8 + t4 * 2;
            if (c0 + 1 < N) {
                float v0 = acc[i][j][0], v1 = acc[i][j][1];
                float v2 = acc[i][j][2], v3 = acc[i][j][3];
                if (roundOut) { v0 = f2tf_f(v0); v1 = f2tf_f(v1); v2 = f2tf_f(v2); v3 = f2tf_f(v3); }
                *(float2*)&C[(size_t)r0 * N + c0] = make_float2(v0, v1);
                *(float2*)&C[(size_t)(r0 + 8) * N + c0] = make_float2(v2, v3);
            } else if (c0 < N) {
                float v0 = acc[i][j][0], v2 = acc[i][j][2];
                if (roundOut) { v0 = f2tf_f(v0); v2 = f2tf_f(v2); }
                C[(size_t)r0 * N + c0] = v0;
                C[(size_t)(r0 + 8) * N + c0] = v2;
            }
        }
    }
}

// ---------------- combined out GEMM (ynorm @ Wcomb) + scatter + residual ----
__global__ __launch_bounds__(256, 2) void gemm_unembed(
    const float* __restrict__ A, const float* __restrict__ B,
    const float* __restrict__ x, const float* __restrict__ ub,
    float* __restrict__ out)
{
    const int N = KPATCH, K = DINNER;
    extern __shared__ uint32_t sm[];
    const uint32_t smb = (uint32_t)__cvta_generic_to_shared(sm);
    const int tid = threadIdx.x, warp = tid >> 5, lane = tid & 31;
    const int warpM = warp >> 2, warpN = warp & 3;
    const int g = lane >> 2, t4 = lane & 3;
    const int bm = blockIdx.y * 128, bn = blockIdx.x * 128;
    const int aRow = tid >> 2, aK = (tid & 3) * 4;
    const int bK = tid >> 5, bCol = (tid & 31) * 4;
    const int bsz = (bn + bCol) < N ? 16 : 0;
    const int T = K >> 4;

    float acc[4][4][4];
#pragma unroll
    for (int i = 0; i < 4; i++)
#pragma unroll
        for (int j = 0; j < 4; j++)
#pragma unroll
            for (int q = 0; q < 4; q++) acc[i][j][q] = 0.f;

#define ISSUE(t) { \
    int s_ = (t) & 3; int k0_ = (t) << 4; \
    uint32_t sa_ = smb + s_ * (ASTG * 4); \
    uint32_t sb_ = smb + (4 * ASTG * 4) + s_ * (BSTG * 4); \
    cpasync16(sa_ + (aRow * 20 + aK) * 4, &A[(size_t)(bm + aRow) * K + k0_ + aK]); \
    cpasync16(sa_ + ((aRow + 64) * 20 + aK) * 4, &A[(size_t)(bm + aRow + 64) * K + k0_ + aK]); \
    cpasync16z(sb_ + (bK * 136 + bCol) * 4, &B[(size_t)(k0_ + bK) * N + bn + bCol], bsz); \
    cpasync16z(sb_ + ((bK + 8) * 136 + bCol) * 4, &B[(size_t)(k0_ + bK + 8) * N + bn + bCol], bsz); }

    ISSUE(0); CP_COMMIT();
    ISSUE(1); CP_COMMIT();
    ISSUE(2); CP_COMMIT();
    CP_WAIT2();
    __syncthreads();

    for (int t = 0; t < T; t++) {
        const int s = t & 3;
        const uint32_t sa = smb + s * (ASTG * 4);
        const uint32_t* Bs = sm + 4 * ASTG + s * BSTG;
#pragma unroll
        for (int kk = 0; kk < 16; kk += 8) {
            uint32_t af[4][4], bf[4][2];
#pragma unroll
            for (int i = 0; i < 4; i++) {
                const int m0 = warpM * 64 + i * 16;
                ldsm4(af[i], sa + ((m0 + (lane & 15)) * 20 + kk + ((lane & 16) >> 2)) * 4);
            }
#pragma unroll
            for (int j = 0; j < 4; j++) {
                const int n0 = warpN * 32 + j * 8;
                bf[j][0] = Bs[(kk + t4) * 136 + n0 + g];
                bf[j][1] = Bs[(kk + t4 + 4) * 136 + n0 + g];
            }
#pragma unroll
            for (int i = 0; i < 4; i++)
#pragma unroll
                for (int j = 0; j < 4; j++)
                    mma8(acc[i][j], af[i], bf[j]);
        }
        if (t + 3 < T) ISSUE(t + 3);
        CP_COMMIT();
        CP_WAIT2();
        __syncthreads();
    }
#undef ISSUE

#pragma unroll
    for (int i = 0; i < 4; i++) {
        const int r0 = bm + warpM * 64 + i * 16 + g;
        const int wp = r0 & 31, hp = (r0 >> 5) & 31, tt = (r0 >> 10) & 7, b = r0 >> 13;
#pragma unroll
        for (int j = 0; j < 4; j++) {
            const int c0 = bn + warpN * 32 + j * 8 + t4 * 2;
            if (c0 < N) {
                const int c = c0 >> 4, i4 = (c0 >> 2) & 3, j0 = c0 & 3;
                const size_t o = ((((size_t)(b * CIN + c) * TT + tt) * HH) + hp * 4 + i4) * WW
                               + (size_t)wp * 4 + j0;
                const float ubv = ub[c];
                float2 xv0 = *(const float2*)&x[o];
                float2 xv1 = *(const float2*)&x[o + 32];
                *(float2*)&out[o]      = make_float2(acc[i][j][0] + ubv + xv0.x,
                                                     acc[i][j][1] + ubv + xv0.y);
                *(float2*)&out[o + 32] = make_float2(acc[i][j][2] + ubv + xv1.x,
                                                     acc[i][j][3] + ubv + xv1.y);
            }
        }
    }
}

// ---------------- patch-embed GEMM: cp.async pipeline + im2col gather -------
__global__ __launch_bounds__(256, 2) void patch_cp(
    const float* __restrict__ x, const float* __restrict__ B,
    float* __restrict__ C, const float* __restrict__ bias)
{
    const int K = KPATCH, N = DM;
    extern __shared__ uint32_t sm[];
    const uint32_t smb = (uint32_t)__cvta_generic_to_shared(sm);
    const int tid = threadIdx.x, warp = tid >> 5, lane = tid & 31;
    const int warpM = warp >> 2, warpN = warp & 3;
    const int g = lane >> 2, t4 = lane & 3;
    const int bm = blockIdx.y * 128, bn = blockIdx.x * 128;
    const int aRow = tid >> 2, aK = (tid & 3) * 4;
    const int bK = tid >> 5, bCol = (tid & 31) * 4;
    const int T = K >> 4;   // 23

    const int r0r = bm + aRow, r1r = bm + aRow + 64;
    const size_t rb0 = ((size_t)((r0r >> 13) * CIN) * TT + ((r0r >> 10) & 7)) * (HH * WW)
                     + (size_t)(((r0r >> 5) & 31) * 4) * WW + (size_t)(r0r & 31) * 4;
    const size_t rb1 = ((size_t)((r1r >> 13) * CIN) * TT + ((r1r >> 10) & 7)) * (HH * WW)
                     + (size_t)(((r1r >> 5) & 31) * 4) * WW + (size_t)(r1r & 31) * 4;

    float acc[4][4][4];
#pragma unroll
    for (int i = 0; i < 4; i++)
#pragma unroll
        for (int j = 0; j < 4; j++)
#pragma unroll
            for (int q = 0; q < 4; q++) acc[i][j][q] = 0.f;

#define ISSUE(t) { \
    int s_ = (t) & 3; int k_ = ((t) << 4) + aK; \
    int c_ = k_ >> 4, i_ = (k_ >> 2) & 3; \
    size_t ao_ = (size_t)c_ * (TT * HH * WW) + (size_t)i_ * WW; \
    int kb_ = (t) << 4; \
    uint32_t sa_ = smb + s_ * (ASTG * 4); \
    uint32_t sb_ = smb + (4 * ASTG * 4) + s_ * (BSTG * 4); \
    cpasync16(sa_ + (aRow * 20 + aK) * 4, &x[rb0 + ao_]); \
    cpasync16(sa_ + ((aRow + 64) * 20 + aK) * 4, &x[rb1 + ao_]); \
    cpasync16(sb_ + (bK * 136 + bCol) * 4, &B[(size_t)(kb_ + bK) * N + bn + bCol]); \
    cpasync16(sb_ + ((bK + 8) * 136 + bCol) * 4, &B[(size_t)(kb_ + bK + 8) * N + bn + bCol]); }

    ISSUE(0); CP_COMMIT();
    ISSUE(1); CP_COMMIT();
    ISSUE(2); CP_COMMIT();
    CP_WAIT2();
    __syncthreads();

    for (int t = 0; t < T; t++) {
        const int s = t & 3;
        const uint32_t sa = smb + s * (ASTG * 4);
        const uint32_t* Bs = sm + 4 * ASTG + s * BSTG;
#pragma unroll
        for (int kk = 0; kk < 16; kk += 8) {
            uint32_t af[4][4], bf[4][2];
#pragma unroll
            for (int i = 0; i < 4; i++) {
                const int m0 = warpM * 64 + i * 16;
                ldsm4(af[i], sa + ((m0 + (lane & 15)) * 20 + kk + ((lane & 16) >> 2)) * 4);
            }
#pragma unroll
            for (int j = 0; j < 4; j++) {
                const int n0 = warpN * 32 + j * 8;
                bf[j][0] = Bs[(kk + t4) * 136 + n0 + g];
                bf[j][1] = Bs[(kk + t4 + 4) * 136 + n0 + g];
            }
#pragma unroll
            for (int i = 0; i < 4; i++)
#pragma unroll
                for (int j = 0; j < 4; j++)
                    mma8(acc[i][j], af[i], bf[j]);
        }
        if (t + 3 < T) ISSUE(t + 3);
        CP_COMMIT();
        CP_WAIT2();
        __syncthreads();
    }
#undef ISSUE

#pragma unroll
    for (int i = 0; i < 4; i++) {
        const int r0 = bm + warpM * 64 + i * 16 + g;
#pragma unroll
        for (int j = 0; j < 4; j++) {
            const int c0 = bn + warpN * 32 + j * 8 + t4 * 2;
            float2 bb = *(const float2*)&bias[c0];
            *(float2*)&C[(size_t)r0 * N + c0] =
                make_float2(f2tf_f(acc[i][j][0] + bb.x), f2tf_f(acc[i][j][1] + bb.y));
            *(float2*)&C[(size_t)(r0 + 8) * N + c0] =
                make_float2(f2tf_f(acc[i][j][2] + bb.x), f2tf_f(acc[i][j][3] + bb.y));
        }
    }
}

// ---------------- merged weight prep (transpose + 3 roundings) --------------
#define NW0 (KPATCH * DM)
#define NW1 (DM * DPROJ)
#define NW2 (DINNER * DM)
#define NW3 (DM * KPATCH)
__global__ void prep_weights(const float* __restrict__ pw, const float* __restrict__ w1,
                             const float* __restrict__ w2, const float* __restrict__ w3)
{
    int i = blockIdx.x * blockDim.x + threadIdx.x;
    if (i < NW0) {
        int k = i / DM, n = i % DM;
        g_patchWT[i] = f2tf_f(pw[n * KPATCH + k]);
    } else if (i < NW0 + NW1) {
        g_Win_r[i - NW0] = f2tf_f(w1[i - NW0]);
    } else if (i < NW0 + NW1 + NW2) {
        g_Wout_r[i - NW0 - NW1] = f2tf_f(w2[i - NW0 - NW1]);
    } else if (i < NW0 + NW1 + NW2 + NW3) {
        g_Wun_r[i - NW0 - NW1 - NW2] = f2tf_f(w3[i - NW0 - NW1 - NW2]);
    }
}

// ---------------- tiled conv1d(w=4)+silu + fused dt/dA (dynamic smem) -------
#define CTOK 16
#define SXS  552   // halo row stride (floats)
#define CONV_SMEM (((CTOK + 3) * SXS + DCONV * CONVDIM + CONVDIM) * 4)  // 52832 B
__global__ __launch_bounds__(256) void conv_tiled(
    const float* __restrict__ cw, const float* __restrict__ cb,
    const float* __restrict__ dtb, const float* __restrict__ alog)
{
    extern __shared__ float csm[];
    float* sx  = csm;
    float* swt = csm + (CTOK + 3) * SXS;
    float* sb  = swt + DCONV * CONVDIM;
    const int m0 = blockIdx.x * CTOK;
    const int l0 = m0 & (LL - 1);
    const int tid = threadIdx.x;

    for (int i = tid; i < CONVDIM; i += 256) {
        float4 w = *(const float4*)&cw[i * 4];
        swt[0 * CONVDIM + i] = w.x; swt[1 * CONVDIM + i] = w.y;
        swt[2 * CONVDIM + i] = w.z; swt[3 * CONVDIM + i] = w.w;
        sb[i] = cb[i];
    }
    for (int t = tid; t < (CTOK + 3) * 136; t += 256) {
        int r = t / 136, c4 = (t % 136) * 4;
        int mm = m0 - 3 + r;
        float4 v = make_float4(0.f, 0.f, 0.f, 0.f);
        if (l0 > 0 || r >= 3)
            v = *(const float4*)&g_zx[(size_t)mm * DPROJ + DINNER + c4];
        *(float4*)&sx[r * SXS + c4] = v;
    }
    if (tid < CTOK * NHEADS) {
        int tok = tid >> 3, hh = tid & 7;
        int m = m0 + tok;
        float raw = g_zx[(size_t)m * DPROJ + DINNER + CONVDIM + hh] + dtb[hh];
        float dt = (raw > 20.f) ? raw : log1pf(expf(raw));
        float da = expf(-expf(alog[hh]) * dt);
        *(float2*)&g_dAdt[(size_t)(m * NHEADS + hh) * 2] = make_float2(da, dt);
    }
    __syncthreads();

    for (int t = tid; t < CTOK * 136; t += 256) {
        int tok = t / 136, c4 = (t % 136) * 4;
        float4 acc = *(const float4*)&sb[c4];
#pragma unroll
        for (int k = 0; k < DCONV; k++) {
            float4 v = *(const float4*)&sx[(tok + k) * SXS + c4];
            float4 w = *(const float4*)&swt[k * CONVDIM + c4];
            acc.x += v.x * w.x; acc.y += v.y * w.y;
            acc.z += v.z * w.z; acc.w += v.w * w.w;
        }
        float4 s;
        s.x = acc.x / (1.f + expf(-acc.x));
        s.y = acc.y / (1.f + expf(-acc.y));
        s.z = acc.z / (1.f + expf(-acc.z));
        s.w = acc.w / (1.f + expf(-acc.w));
        *(float4*)&g_xBCs[(size_t)(m0 + tok) * CONVDIM + c4] = s;
    }
}

// ---------------- scan phase 1: chunk-end states, 4-deep prefetch -----------
__global__ __launch_bounds__(512) void scan_phase1()
{
    const int c = blockIdx.x, b = blockIdx.y;
    const int w = threadIdx.x >> 5, lane = threadIdx.x & 31;
    const int h = w >> 1;
    const int p = ((w & 1) << 5) + lane;
    const int d = h * HEADDIM + p;
    __shared__ float sB[16][2][16];
    float hreg[DSTATE];
#pragma unroll
    for (int n = 0; n < DSTATE; n++) hreg[n] = 0.f;
    float runD = 1.f;
    const int m0 = b * LL + c * QCHUNK;

    float svr[4], bcr[4];
    float2 ddr[4];
#pragma unroll
    for (int j = 0; j < 4; j++) {
        svr[j] = g_xBCs[(size_t)(m0 + j) * CONVDIM + d];
        ddr[j] = *(const float2*)&g_dAdt[(size_t)((m0 + j) * NHEADS + h) * 2];
        if (lane < 16) bcr[j] = g_xBCs[(size_t)(m0 + j) * CONVDIM + DINNER + lane];
    }
    if (lane < 16) sB[w][0][lane] = bcr[0];
    __syncwarp();

    for (int i = 0; i < QCHUNK; i++) {
        const int j = i & 3;
        const float da = ddr[j].x;
        const float xv = svr[j] * ddr[j].y;
        runD *= da;
        // issue loads for token i+4 into slot j (just consumed)
        if (i + 4 < QCHUNK) {
            svr[j] = g_xBCs[(size_t)(m0 + i + 4) * CONVDIM + d];
            ddr[j] = *(const float2*)&g_dAdt[(size_t)((m0 + i + 4) * NHEADS + h) * 2];
            if (lane < 16) bcr[j] = g_xBCs[(size_t)(m0 + i + 4) * CONVDIM + DINNER + lane];
        }
#pragma unroll
        for (int n = 0; n < DSTATE; n++)
            hreg[n] = da * hreg[n] + xv * sB[w][i & 1][n];
        // stage next token's B (loaded 3 iters ago) into the other smem buffer
        if (i + 1 < QCHUNK && lane < 16) sB[w][(i + 1) & 1][lane] = bcr[(i + 1) & 3];
        __syncwarp();
    }
    const int sb = ((b * NCHUNK + c) * NHEADS + h) * HEADDIM + p;
#pragma unroll
    for (int n = 0; n < DSTATE; n++) g_S[(size_t)sb * DSTATE + n] = hreg[n];
    if (p == 0) g_P[(b * NCHUNK + c) * NHEADS + h] = runD;
}

// ---------------- scan phase 2: deep-prefetch serial recurrence -------------
__global__ __launch_bounds__(1024) void scan_phase2()
{
    const int b = blockIdx.x >> 3, h = blockIdx.x & 7;
    const int tid = threadIdx.x;
    const size_t base0 = (size_t)((b * NCHUNK + 0) * NHEADS + h) * (HEADDIM * DSTATE) + tid;
    const size_t stride = (size_t)NHEADS * HEADDIM * DSTATE;
    const int pb = b * NCHUNK * NHEADS + h;

    float sbuf[8], pbuf[8];
#pragma unroll
    for (int j = 0; j < 8; j++) {
        sbuf[j] = g_S[base0 + (size_t)j * stride];
        pbuf[j] = g_P[pb + j * NHEADS];
    }
    float val = 0.f;
#pragma unroll 8
    for (int c = 0; c < NCHUNK; c++) {
        const int j = c & 7;
        g_hinit[base0 + (size_t)c * stride] = val;
        val = pbuf[j] * val + sbuf[j];
        if (c + 8 < NCHUNK) {
            sbuf[j] = g_S[base0 + (size_t)(c + 8) * stride];
            pbuf[j] = g_P[pb + (c + 8) * NHEADS];
        }
    }
}

// ---------------- scan finish: 4-deep prefetch + skip + gate + RMSnorm ------
__global__ __launch_bounds__(512) void scan_finish(
    const float* __restrict__ Dp, const float* __restrict__ nw)
{
    const int c = blockIdx.x, b = blockIdx.y;
    const int tid = threadIdx.x;
    const int h = tid >> 6, p = tid & 63;
    const int warp = tid >> 5, lane = tid & 31;
    __shared__ float sBC[2][32];
    __shared__ float sred[2][16];

    float hreg[DSTATE];
    {
        const float* hi = &g_hinit[((size_t)((b * NCHUNK + c) * NHEADS + h) * HEADDIM + p) * DSTATE];
#pragma unroll
        for (int n = 0; n < DSTATE; n += 4) {
            float4 v = *(const float4*)&hi[n];
            hreg[n] = v.x; hreg[n+1] = v.y; hreg[n+2] = v.z; hreg[n+3] = v.w;
        }
    }
    const float Dpv = Dp[h];
    const float nwv = nw[tid];
    const int m0 = b * LL + c * QCHUNK;

    float svr[4], zvr[4], bcr[4];
    float2 ddr[4];
#pragma unroll
    for (int j = 0; j < 4; j++) {
        svr[j] = g_xBCs[(size_t)(m0 + j) * CONVDIM + tid];
        zvr[j] = g_zx[(size_t)(m0 + j) * DPROJ + tid];
        ddr[j] = *(const float2*)&g_dAdt[(size_t)((m0 + j) * NHEADS + h) * 2];
        if (tid < 32) bcr[j] = g_xBCs[(size_t)(m0 + j) * CONVDIM + DINNER + tid];
    }
    if (tid < 32) sBC[0][tid] = bcr[0];
    __syncthreads();

    for (int i = 0; i < QCHUNK; i++) {
        const int m = m0 + i;
        const int j = i & 3;
        const float da = ddr[j].x;
        const float xv = svr[j] * ddr[j].y;
        const float svv = svr[j];
        const float zvv = zvr[j];
        // issue loads for token i+4 into slot j
        if (i + 4 < QCHUNK) {
            svr[j] = g_xBCs[(size_t)(m + 4) * CONVDIM + tid];
            zvr[j] = g_zx[(size_t)(m + 4) * DPROJ + tid];
            ddr[j] = *(const float2*)&g_dAdt[(size_t)((m + 4) * NHEADS + h) * 2];
            if (tid < 32) bcr[j] = g_xBCs[(size_t)(m + 4) * CONVDIM + DINNER + tid];
        }
        float y0 = 0.f, y1 = 0.f;
#pragma unroll
        for (int n = 0; n < DSTATE; n += 2) {
            hreg[n]     = da * hreg[n]     + xv * sBC[i & 1][n];
            hreg[n + 1] = da * hreg[n + 1] + xv * sBC[i & 1][n + 1];
            y0 += hreg[n]     * sBC[i & 1][16 + n];
            y1 += hreg[n + 1] * sBC[i & 1][16 + n + 1];
        }
        const float y = y0 + y1 + Dpv * svv;
        const float yg = y * (zvv / (1.f + expf(-zvv)));

        float v = yg * yg;
#pragma unroll
        for (int o = 16; o; o >>= 1) v += __shfl_xor_sync(0xffffffffu, v, o);
        if (lane == 0) sred[i & 1][warp] = v;
        // stage next token's BC (loaded 3 iters ago)
        if (i + 1 < QCHUNK && tid < 32) sBC[(i + 1) & 1][tid] = bcr[(i + 1) & 3];
        __syncthreads();

        float tot = 0.f;
#pragma unroll
        for (int ww = 0; ww < 16; ww++) tot += sred[i & 1][ww];
        const float rstd = rsqrtf(tot * (1.f / (float)DINNER) + 1e-5f);
        g_ynorm[(size_t)m * DINNER + tid] = f2tf_f(yg * rstd * nwv);
    }
}

// ---------------- driver ---------------------------------------------------
extern "C" void kernel_launch(void* const* d_in, const int* in_sizes, int n_in,
                              void* d_out, int out_size)
{
    const float* x       = (const float*)d_in[0];
    const float* patch_w = (const float*)d_in[1];
    const float* patch_b = (const float*)d_in[2];
    const float* W_in    = (const float*)d_in[3];
    const float* conv_w  = (const float*)d_in[4];
    const float* conv_b  = (const float*)d_in[5];
    const float* dt_bias = (const float*)d_in[6];
    const float* A_log   = (const float*)d_in[7];
    const float* D_param = (const float*)d_in[8];
    const float* norm_w  = (const float*)d_in[9];
    const float* W_out   = (const float*)d_in[10];
    const float* unemb_w = (const float*)d_in[11];
    const float* unemb_b = (const float*)d_in[12];
    float* out = (float*)d_out;

    float *pWT, *pxs, *pzx, *pyn, *pWin, *pWout, *pWun, *pWcomb;
    cudaGetSymbolAddress((void**)&pWT,    g_patchWT);
    cudaGetSymbolAddress((void**)&pxs,    g_xs);
    cudaGetSymbolAddress((void**)&pzx,    g_zx);
    cudaGetSymbolAddress((void**)&pyn,    g_ynorm);
    cudaGetSymbolAddress((void**)&pWin,   g_Win_r);
    cudaGetSymbolAddress((void**)&pWout,  g_Wout_r);
    cudaGetSymbolAddress((void**)&pWun,   g_Wun_r);
    cudaGetSymbolAddress((void**)&pWcomb, g_Wcomb);

    cudaFuncSetAttribute(gemm_cp, cudaFuncAttributeMaxDynamicSharedMemorySize, GEMM_SMEM);
    cudaFuncSetAttribute(gemm_unembed, cudaFuncAttributeMaxDynamicSharedMemorySize, GEMM_SMEM);
    cudaFuncSetAttribute(patch_cp, cudaFuncAttributeMaxDynamicSharedMemorySize, GEMM_SMEM);
    cudaFuncSetAttribute(conv_tiled, cudaFuncAttributeMaxDynamicSharedMemorySize, CONV_SMEM);

    // weight prep (transpose + tf32 pre-rounding, single launch)
    prep_weights<<<(NW0 + NW1 + NW2 + NW3 + 255) / 256, 256>>>(patch_w, W_in, W_out, unemb_w);

    // combined output weight: Wcomb = W_out @ W_un  [512, 368]
    gemm_cp<<<dim3(3, DINNER / 128), 256, GEMM_SMEM>>>(
        pWout, pWun, pWcomb, DINNER, KPATCH, DM, 1);

    // patch embed (cp.async pipeline with fused im2col gather)
    patch_cp<<<dim3(2, MTOK / 128), 256, GEMM_SMEM>>>(x, pWT, pxs, patch_b);

    // in_proj
    gemm_cp<<<dim3((DPROJ + 127) / 128, MTOK / 128), 256, GEMM_SMEM>>>(
        pxs, pWin, pzx, MTOK, DPROJ, DM, 0);

    // conv + silu + dt/dA (tiled, fused)
    conv_tiled<<<MTOK / CTOK, 256, CONV_SMEM>>>(conv_w, conv_b, dt_bias, A_log);

    // chunked SSM scan + fused gate/RMSnorm
    scan_phase1<<<dim3(NCHUNK, BB), 512>>>();
    scan_phase2<<<BB * NHEADS, 1024>>>();
    scan_finish<<<dim3(NCHUNK, BB), 512>>>(D_param, norm_w);

    // combined out_proj+unembed GEMM + scatter + bias + residual
    gemm_unembed<<<dim3(3, MTOK / 128), 256, GEMM_SMEM>>>(pyn, pWcomb, x, unemb_b, out);
}

// round 15
// speedup vs baseline: 1.1429x; 1.1429x over previous
#include <cuda_runtime.h>
#include <math.h>
#include <stdint.h>

// ---------------- problem constants ----------------
#define BB      4
#define CIN     23
#define TT      8
#define HH      128
#define WW      128
#define DM      256
#define DSTATE  16
#define DCONV   4
#define DINNER  512
#define HEADDIM 64
#define NHEADS  8
#define CONVDIM 544
#define DPROJ   1064
#define HP      32
#define WP      32
#define LL      8192
#define MTOK    32768
#define KPATCH  368
#define QCHUNK  64
#define NCHUNK  128
#define NOUT    (BB*CIN*TT*HH*WW)

// ---------------- scratch ----------------
__device__ __align__(128) float g_patchWT[KPATCH * DM];
__device__ __align__(128) float g_Win_r [DM * DPROJ];
__device__ __align__(128) float g_Wout_r[DINNER * DM];
__device__ __align__(128) float g_Wun_r [DM * KPATCH];
__device__ __align__(128) float g_Wcomb [DINNER * KPATCH];    // W_out @ W_un (tf32)
__device__ __align__(128) float g_xs    [MTOK * DM];
__device__ __align__(128) float g_zx    [MTOK * DPROJ];
__device__ __align__(128) float g_xBCs  [MTOK * CONVDIM];
__device__ __align__(128) float g_dAdt  [MTOK * NHEADS * 2];   // (dA, dt) pairs
__device__ __align__(128) float g_S     [BB*NCHUNK*NHEADS*HEADDIM*DSTATE];
__device__ __align__(128) float g_P     [BB*NCHUNK*NHEADS];
__device__ __align__(128) float g_hinit [BB*NCHUNK*NHEADS*HEADDIM*DSTATE];
__device__ __align__(128) float g_ynorm [MTOK * DINNER];

// ---------------- helpers ---------------------------------------------------
__device__ __forceinline__ uint32_t f2tf(float f) {
    uint32_t u;
    asm("cvt.rna.tf32.f32 %0, %1;" : "=r"(u) : "f"(f));
    return u;
}
__device__ __forceinline__ float f2tf_f(float f) { return __uint_as_float(f2tf(f)); }

__device__ __forceinline__ void mma8(float* c, const uint32_t* a, const uint32_t* b) {
    asm volatile(
        "mma.sync.aligned.m16n8k8.row.col.f32.tf32.tf32.f32 "
        "{%0,%1,%2,%3},{%4,%5,%6,%7},{%8,%9},{%0,%1,%2,%3};"
        : "+f"(c[0]), "+f"(c[1]), "+f"(c[2]), "+f"(c[3])
        : "r"(a[0]), "r"(a[1]), "r"(a[2]), "r"(a[3]), "r"(b[0]), "r"(b[1]));
}
__device__ __forceinline__ void ldsm4(uint32_t* r, uint32_t addr) {
    asm volatile("ldmatrix.sync.aligned.m8n8.x4.shared.b16 {%0,%1,%2,%3},[%4];"
                 : "=r"(r[0]), "=r"(r[1]), "=r"(r[2]), "=r"(r[3]) : "r"(addr));
}
__device__ __forceinline__ void cpasync16(uint32_t saddr, const void* gaddr) {
    asm volatile("cp.async.cg.shared.global [%0], [%1], 16;\n" :: "r"(saddr), "l"(gaddr));
}
__device__ __forceinline__ void cpasync16z(uint32_t saddr, const void* gaddr, int sz) {
    asm volatile("cp.async.cg.shared.global [%0], [%1], 16, %2;\n"
                 :: "r"(saddr), "l"(gaddr), "r"(sz));
}
#define CP_COMMIT() asm volatile("cp.async.commit_group;\n" ::: "memory")
#define CP_WAIT2()  asm volatile("cp.async.wait_group 2;\n" ::: "memory")

#define ASTG 2560   // 128*20
#define BSTG 2176   // 16*136
#define GEMM_SMEM ((4*ASTG + 4*BSTG) * 4)

// ---------------- generic cp.async TF32 GEMM (inputs pre-rounded) ----------
__global__ __launch_bounds__(256, 2) void gemm_cp(
    const float* __restrict__ A, const float* __restrict__ B,
    float* __restrict__ C, int M, int N, int K, int roundOut)
{
    extern __shared__ uint32_t sm[];
    const uint32_t smb = (uint32_t)__cvta_generic_to_shared(sm);
    const int tid = threadIdx.x, warp = tid >> 5, lane = tid & 31;
    const int warpM = warp >> 2, warpN = warp & 3;
    const int g = lane >> 2, t4 = lane & 3;
    const int bm = blockIdx.y * 128, bn = blockIdx.x * 128;
    const int aRow = tid >> 2, aK = (tid & 3) * 4;
    const int bK = tid >> 5, bCol = (tid & 31) * 4;
    const int bsz = (bn + bCol) < N ? 16 : 0;
    const int T = K >> 4;

    float acc[4][4][4];
#pragma unroll
    for (int i = 0; i < 4; i++)
#pragma unroll
        for (int j = 0; j < 4; j++)
#pragma unroll
            for (int q = 0; q < 4; q++) acc[i][j][q] = 0.f;

#define ISSUE(t) { \
    int s_ = (t) & 3; int k0_ = (t) << 4; \
    uint32_t sa_ = smb + s_ * (ASTG * 4); \
    uint32_t sb_ = smb + (4 * ASTG * 4) + s_ * (BSTG * 4); \
    cpasync16(sa_ + (aRow * 20 + aK) * 4, &A[(size_t)(bm + aRow) * K + k0_ + aK]); \
    cpasync16(sa_ + ((aRow + 64) * 20 + aK) * 4, &A[(size_t)(bm + aRow + 64) * K + k0_ + aK]); \
    cpasync16z(sb_ + (bK * 136 + bCol) * 4, &B[(size_t)(k0_ + bK) * N + bn + bCol], bsz); \
    cpasync16z(sb_ + ((bK + 8) * 136 + bCol) * 4, &B[(size_t)(k0_ + bK + 8) * N + bn + bCol], bsz); }

    ISSUE(0); CP_COMMIT();
    ISSUE(1); CP_COMMIT();
    ISSUE(2); CP_COMMIT();
    CP_WAIT2();
    __syncthreads();

    for (int t = 0; t < T; t++) {
        const int s = t & 3;
        const uint32_t sa = smb + s * (ASTG * 4);
        const uint32_t* Bs = sm + 4 * ASTG + s * BSTG;
#pragma unroll
        for (int kk = 0; kk < 16; kk += 8) {
            uint32_t af[4][4], bf[4][2];
#pragma unroll
            for (int i = 0; i < 4; i++) {
                const int m0 = warpM * 64 + i * 16;
                ldsm4(af[i], sa + ((m0 + (lane & 15)) * 20 + kk + ((lane & 16) >> 2)) * 4);
            }
#pragma unroll
            for (int j = 0; j < 4; j++) {
                const int n0 = warpN * 32 + j * 8;
                bf[j][0] = Bs[(kk + t4) * 136 + n0 + g];
                bf[j][1] = Bs[(kk + t4 + 4) * 136 + n0 + g];
            }
#pragma unroll
            for (int i = 0; i < 4; i++)
#pragma unroll
                for (int j = 0; j < 4; j++)
                    mma8(acc[i][j], af[i], bf[j]);
        }
        if (t + 3 < T) ISSUE(t + 3);
        CP_COMMIT();
        CP_WAIT2();
        __syncthreads();
    }
#undef ISSUE

#pragma unroll
    for (int i = 0; i < 4; i++) {
        const int r0 = bm + warpM * 64 + i * 16 + g;
#pragma unroll
        for (int j = 0; j < 4; j++) {
            const int c0 = bn + warpN * 32 + j * 8 + t4 * 2;
            if (c0 + 1 < N) {
                float v0 = acc[i][j][0], v1 = acc[i][j][1];
                float v2 = acc[i][j][2], v3 = acc[i][j][3];
                if (roundOut) { v0 = f2tf_f(v0); v1 = f2tf_f(v1); v2 = f2tf_f(v2); v3 = f2tf_f(v3); }
                *(float2*)&C[(size_t)r0 * N + c0] = make_float2(v0, v1);
                *(float2*)&C[(size_t)(r0 + 8) * N + c0] = make_float2(v2, v3);
            } else if (c0 < N) {
                float v0 = acc[i][j][0], v2 = acc[i][j][2];
                if (roundOut) { v0 = f2tf_f(v0); v2 = f2tf_f(v2); }
                C[(size_t)r0 * N + c0] = v0;
                C[(size_t)(r0 + 8) * N + c0] = v2;
            }
        }
    }
}

// ---------------- combined out GEMM (ynorm @ Wcomb) + scatter + residual ----
__global__ __launch_bounds__(256, 2) void gemm_unembed(
    const float* __restrict__ A, const float* __restrict__ B,
    const float* __restrict__ x, const float* __restrict__ ub,
    float* __restrict__ out)
{
    const int N = KPATCH, K = DINNER;
    extern __shared__ uint32_t sm[];
    const uint32_t smb = (uint32_t)__cvta_generic_to_shared(sm);
    const int tid = threadIdx.x, warp = tid >> 5, lane = tid & 31;
    const int warpM = warp >> 2, warpN = warp & 3;
    const int g = lane >> 2, t4 = lane & 3;
    const int bm = blockIdx.y * 128, bn = blockIdx.x * 128;
    const int aRow = tid >> 2, aK = (tid & 3) * 4;
    const int bK = tid >> 5, bCol = (tid & 31) * 4;
    const int bsz = (bn + bCol) < N ? 16 : 0;
    const int T = K >> 4;

    float acc[4][4][4];
#pragma unroll
    for (int i = 0; i < 4; i++)
#pragma unroll
        for (int j = 0; j < 4; j++)
#pragma unroll
            for (int q = 0; q < 4; q++) acc[i][j][q] = 0.f;

#define ISSUE(t) { \
    int s_ = (t) & 3; int k0_ = (t) << 4; \
    uint32_t sa_ = smb + s_ * (ASTG * 4); \
    uint32_t sb_ = smb + (4 * ASTG * 4) + s_ * (BSTG * 4); \
    cpasync16(sa_ + (aRow * 20 + aK) * 4, &A[(size_t)(bm + aRow) * K + k0_ + aK]); \
    cpasync16(sa_ + ((aRow + 64) * 20 + aK) * 4, &A[(size_t)(bm + aRow + 64) * K + k0_ + aK]); \
    cpasync16z(sb_ + (bK * 136 + bCol) * 4, &B[(size_t)(k0_ + bK) * N + bn + bCol], bsz); \
    cpasync16z(sb_ + ((bK + 8) * 136 + bCol) * 4, &B[(size_t)(k0_ + bK + 8) * N + bn + bCol], bsz); }

    ISSUE(0); CP_COMMIT();
    ISSUE(1); CP_COMMIT();
    ISSUE(2); CP_COMMIT();
    CP_WAIT2();
    __syncthreads();

    for (int t = 0; t < T; t++) {
        const int s = t & 3;
        const uint32_t sa = smb + s * (ASTG * 4);
        const uint32_t* Bs = sm + 4 * ASTG + s * BSTG;
#pragma unroll
        for (int kk = 0; kk < 16; kk += 8) {
            uint32_t af[4][4], bf[4][2];
#pragma unroll
            for (int i = 0; i < 4; i++) {
                const int m0 = warpM * 64 + i * 16;
                ldsm4(af[i], sa + ((m0 + (lane & 15)) * 20 + kk + ((lane & 16) >> 2)) * 4);
            }
#pragma unroll
            for (int j = 0; j < 4; j++) {
                const int n0 = warpN * 32 + j * 8;
                bf[j][0] = Bs[(kk + t4) * 136 + n0 + g];
                bf[j][1] = Bs[(kk + t4 + 4) * 136 + n0 + g];
            }
#pragma unroll
            for (int i = 0; i < 4; i++)
#pragma unroll
                for (int j = 0; j < 4; j++)
                    mma8(acc[i][j], af[i], bf[j]);
        }
        if (t + 3 < T) ISSUE(t + 3);
        CP_COMMIT();
        CP_WAIT2();
        __syncthreads();
    }
#undef ISSUE

#pragma unroll
    for (int i = 0; i < 4; i++) {
        const int r0 = bm + warpM * 64 + i * 16 + g;
        const int wp = r0 & 31, hp = (r0 >> 5) & 31, tt = (r0 >> 10) & 7, b = r0 >> 13;
#pragma unroll
        for (int j = 0; j < 4; j++) {
            const int c0 = bn + warpN * 32 + j * 8 + t4 * 2;
            if (c0 < N) {
                const int c = c0 >> 4, i4 = (c0 >> 2) & 3, j0 = c0 & 3;
                const size_t o = ((((size_t)(b * CIN + c) * TT + tt) * HH) + hp * 4 + i4) * WW
                               + (size_t)wp * 4 + j0;
                const float ubv = ub[c];
                float2 xv0 = *(const float2*)&x[o];
                float2 xv1 = *(const float2*)&x[o + 32];
                *(float2*)&out[o]      = make_float2(acc[i][j][0] + ubv + xv0.x,
                                                     acc[i][j][1] + ubv + xv0.y);
                *(float2*)&out[o + 32] = make_float2(acc[i][j][2] + ubv + xv1.x,
                                                     acc[i][j][3] + ubv + xv1.y);
            }
        }
    }
}

// ---------------- patch-embed GEMM: cp.async pipeline + im2col gather -------
__global__ __launch_bounds__(256, 2) void patch_cp(
    const float* __restrict__ x, const float* __restrict__ B,
    float* __restrict__ C, const float* __restrict__ bias)
{
    const int K = KPATCH, N = DM;
    extern __shared__ uint32_t sm[];
    const uint32_t smb = (uint32_t)__cvta_generic_to_shared(sm);
    const int tid = threadIdx.x, warp = tid >> 5, lane = tid & 31;
    const int warpM = warp >> 2, warpN = warp & 3;
    const int g = lane >> 2, t4 = lane & 3;
    const int bm = blockIdx.y * 128, bn = blockIdx.x * 128;
    const int aRow = tid >> 2, aK = (tid & 3) * 4;
    const int bK = tid >> 5, bCol = (tid & 31) * 4;
    const int T = K >> 4;   // 23

    const int r0r = bm + aRow, r1r = bm + aRow + 64;
    const size_t rb0 = ((size_t)((r0r >> 13) * CIN) * TT + ((r0r >> 10) & 7)) * (HH * WW)
                     + (size_t)(((r0r >> 5) & 31) * 4) * WW + (size_t)(r0r & 31) * 4;
    const size_t rb1 = ((size_t)((r1r >> 13) * CIN) * TT + ((r1r >> 10) & 7)) * (HH * WW)
                     + (size_t)(((r1r >> 5) & 31) * 4) * WW + (size_t)(r1r & 31) * 4;

    float acc[4][4][4];
#pragma unroll
    for (int i = 0; i < 4; i++)
#pragma unroll
        for (int j = 0; j < 4; j++)
#pragma unroll
            for (int q = 0; q < 4; q++) acc[i][j][q] = 0.f;

#define ISSUE(t) { \
    int s_ = (t) & 3; int k_ = ((t) << 4) + aK; \
    int c_ = k_ >> 4, i_ = (k_ >> 2) & 3; \
    size_t ao_ = (size_t)c_ * (TT * HH * WW) + (size_t)i_ * WW; \
    int kb_ = (t) << 4; \
    uint32_t sa_ = smb + s_ * (ASTG * 4); \
    uint32_t sb_ = smb + (4 * ASTG * 4) + s_ * (BSTG * 4); \
    cpasync16(sa_ + (aRow * 20 + aK) * 4, &x[rb0 + ao_]); \
    cpasync16(sa_ + ((aRow + 64) * 20 + aK) * 4, &x[rb1 + ao_]); \
    cpasync16(sb_ + (bK * 136 + bCol) * 4, &B[(size_t)(kb_ + bK) * N + bn + bCol]); \
    cpasync16(sb_ + ((bK + 8) * 136 + bCol) * 4, &B[(size_t)(kb_ + bK + 8) * N + bn + bCol]); }

    ISSUE(0); CP_COMMIT();
    ISSUE(1); CP_COMMIT();
    ISSUE(2); CP_COMMIT();
    CP_WAIT2();
    __syncthreads();

    for (int t = 0; t < T; t++) {
        const int s = t & 3;
        const uint32_t sa = smb + s * (ASTG * 4);
        const uint32_t* Bs = sm + 4 * ASTG + s * BSTG;
#pragma unroll
        for (int kk = 0; kk < 16; kk += 8) {
            uint32_t af[4][4], bf[4][2];
#pragma unroll
            for (int i = 0; i < 4; i++) {
                const int m0 = warpM * 64 + i * 16;
                ldsm4(af[i], sa + ((m0 + (lane & 15)) * 20 + kk + ((lane & 16) >> 2)) * 4);
            }
#pragma unroll
            for (int j = 0; j < 4; j++) {
                const int n0 = warpN * 32 + j * 8;
                bf[j][0] = Bs[(kk + t4) * 136 + n0 + g];
                bf[j][1] = Bs[(kk + t4 + 4) * 136 + n0 + g];
            }
#pragma unroll
            for (int i = 0; i < 4; i++)
#pragma unroll
                for (int j = 0; j < 4; j++)
                    mma8(acc[i][j], af[i], bf[j]);
        }
        if (t + 3 < T) ISSUE(t + 3);
        CP_COMMIT();
        CP_WAIT2();
        __syncthreads();
    }
#undef ISSUE

#pragma unroll
    for (int i = 0; i < 4; i++) {
        const int r0 = bm + warpM * 64 + i * 16 + g;
#pragma unroll
        for (int j = 0; j < 4; j++) {
            const int c0 = bn + warpN * 32 + j * 8 + t4 * 2;
            float2 bb = *(const float2*)&bias[c0];
            *(float2*)&C[(size_t)r0 * N + c0] =
                make_float2(f2tf_f(acc[i][j][0] + bb.x), f2tf_f(acc[i][j][1] + bb.y));
            *(float2*)&C[(size_t)(r0 + 8) * N + c0] =
                make_float2(f2tf_f(acc[i][j][2] + bb.x), f2tf_f(acc[i][j][3] + bb.y));
        }
    }
}

// ---------------- merged weight prep (transpose + 3 roundings) --------------
#define NW0 (KPATCH * DM)
#define NW1 (DM * DPROJ)
#define NW2 (DINNER * DM)
#define NW3 (DM * KPATCH)
__global__ void prep_weights(const float* __restrict__ pw, const float* __restrict__ w1,
                             const float* __restrict__ w2, const float* __restrict__ w3)
{
    int i = blockIdx.x * blockDim.x + threadIdx.x;
    if (i < NW0) {
        int k = i / DM, n = i % DM;
        g_patchWT[i] = f2tf_f(pw[n * KPATCH + k]);
    } else if (i < NW0 + NW1) {
        g_Win_r[i - NW0] = f2tf_f(w1[i - NW0]);
    } else if (i < NW0 + NW1 + NW2) {
        g_Wout_r[i - NW0 - NW1] = f2tf_f(w2[i - NW0 - NW1]);
    } else if (i < NW0 + NW1 + NW2 + NW3) {
        g_Wun_r[i - NW0 - NW1 - NW2] = f2tf_f(w3[i - NW0 - NW1 - NW2]);
    }
}

// ---------------- tiled conv1d(w=4)+silu + fused dt/dA (dynamic smem) -------
#define CTOK 16
#define SXS  552   // halo row stride (floats)
#define CONV_SMEM (((CTOK + 3) * SXS + DCONV * CONVDIM + CONVDIM) * 4)  // 52832 B
__global__ __launch_bounds__(256) void conv_tiled(
    const float* __restrict__ cw, const float* __restrict__ cb,
    const float* __restrict__ dtb, const float* __restrict__ alog)
{
    extern __shared__ float csm[];
    float* sx  = csm;
    float* swt = csm + (CTOK + 3) * SXS;
    float* sb  = swt + DCONV * CONVDIM;
    const int m0 = blockIdx.x * CTOK;
    const int l0 = m0 & (LL - 1);
    const int tid = threadIdx.x;

    for (int i = tid; i < CONVDIM; i += 256) {
        float4 w = *(const float4*)&cw[i * 4];
        swt[0 * CONVDIM + i] = w.x; swt[1 * CONVDIM + i] = w.y;
        swt[2 * CONVDIM + i] = w.z; swt[3 * CONVDIM + i] = w.w;
        sb[i] = cb[i];
    }
    for (int t = tid; t < (CTOK + 3) * 136; t += 256) {
        int r = t / 136, c4 = (t % 136) * 4;
        int mm = m0 - 3 + r;
        float4 v = make_float4(0.f, 0.f, 0.f, 0.f);
        if (l0 > 0 || r >= 3)
            v = *(const float4*)&g_zx[(size_t)mm * DPROJ + DINNER + c4];
        *(float4*)&sx[r * SXS + c4] = v;
    }
    if (tid < CTOK * NHEADS) {
        int tok = tid >> 3, hh = tid & 7;
        int m = m0 + tok;
        float raw = g_zx[(size_t)m * DPROJ + DINNER + CONVDIM + hh] + dtb[hh];
        float dt = (raw > 20.f) ? raw : log1pf(expf(raw));
        float da = expf(-expf(alog[hh]) * dt);
        *(float2*)&g_dAdt[(size_t)(m * NHEADS + hh) * 2] = make_float2(da, dt);
    }
    __syncthreads();

    for (int t = tid; t < CTOK * 136; t += 256) {
        int tok = t / 136, c4 = (t % 136) * 4;
        float4 acc = *(const float4*)&sb[c4];
#pragma unroll
        for (int k = 0; k < DCONV; k++) {
            float4 v = *(const float4*)&sx[(tok + k) * SXS + c4];
            float4 w = *(const float4*)&swt[k * CONVDIM + c4];
            acc.x += v.x * w.x; acc.y += v.y * w.y;
            acc.z += v.z * w.z; acc.w += v.w * w.w;
        }
        float4 s;
        s.x = acc.x / (1.f + expf(-acc.x));
        s.y = acc.y / (1.f + expf(-acc.y));
        s.z = acc.z / (1.f + expf(-acc.z));
        s.w = acc.w / (1.f + expf(-acc.w));
        *(float4*)&g_xBCs[(size_t)(m0 + tok) * CONVDIM + c4] = s;
    }
}

// ---------------- scan phase 1: chunk-end states, 4-deep const-idx prefetch -
__global__ __launch_bounds__(512) void scan_phase1()
{
    const int c = blockIdx.x, b = blockIdx.y;
    const int w = threadIdx.x >> 5, lane = threadIdx.x & 31;
    const int h = w >> 1;
    const int p = ((w & 1) << 5) + lane;
    const int d = h * HEADDIM + p;
    __shared__ float sB[16][2][16];
    float hreg[DSTATE];
#pragma unroll
    for (int n = 0; n < DSTATE; n++) hreg[n] = 0.f;
    float runD = 1.f;
    const int m0 = b * LL + c * QCHUNK;

    float sv0, sv1, sv2, sv3, bc0, bc1, bc2, bc3;
    float2 dd0, dd1, dd2, dd3;
    sv0 = g_xBCs[(size_t)(m0 + 0) * CONVDIM + d];
    sv1 = g_xBCs[(size_t)(m0 + 1) * CONVDIM + d];
    sv2 = g_xBCs[(size_t)(m0 + 2) * CONVDIM + d];
    sv3 = g_xBCs[(size_t)(m0 + 3) * CONVDIM + d];
    dd0 = *(const float2*)&g_dAdt[(size_t)((m0 + 0) * NHEADS + h) * 2];
    dd1 = *(const float2*)&g_dAdt[(size_t)((m0 + 1) * NHEADS + h) * 2];
    dd2 = *(const float2*)&g_dAdt[(size_t)((m0 + 2) * NHEADS + h) * 2];
    dd3 = *(const float2*)&g_dAdt[(size_t)((m0 + 3) * NHEADS + h) * 2];
    bc0 = bc1 = bc2 = bc3 = 0.f;
    if (lane < 16) {
        bc0 = g_xBCs[(size_t)(m0 + 0) * CONVDIM + DINNER + lane];
        bc1 = g_xBCs[(size_t)(m0 + 1) * CONVDIM + DINNER + lane];
        bc2 = g_xBCs[(size_t)(m0 + 2) * CONVDIM + DINNER + lane];
        bc3 = g_xBCs[(size_t)(m0 + 3) * CONVDIM + DINNER + lane];
        sB[w][0][lane] = bc0;
    }
    __syncwarp();

#define SCAN1_STEP(i, SV, BC, DD, BCN) { \
    const float da_ = DD.x; \
    const float xv_ = SV * DD.y; \
    runD *= da_; \
    if ((i) + 4 < QCHUNK) { \
        SV = g_xBCs[(size_t)(m0 + (i) + 4) * CONVDIM + d]; \
        DD = *(const float2*)&g_dAdt[(size_t)((m0 + (i) + 4) * NHEADS + h) * 2]; \
        if (lane < 16) BC = g_xBCs[(size_t)(m0 + (i) + 4) * CONVDIM + DINNER + lane]; \
    } \
    _Pragma("unroll") \
    for (int n = 0; n < DSTATE; n++) \
        hreg[n] = da_ * hreg[n] + xv_ * sB[w][(i) & 1][n]; \
    if ((i) + 1 < QCHUNK && lane < 16) sB[w][((i) + 1) & 1][lane] = BCN; \
    __syncwarp(); }

    for (int i0 = 0; i0 < QCHUNK; i0 += 4) {
        SCAN1_STEP(i0 + 0, sv0, bc0, dd0, bc1);
        SCAN1_STEP(i0 + 1, sv1, bc1, dd1, bc2);
        SCAN1_STEP(i0 + 2, sv2, bc2, dd2, bc3);
        SCAN1_STEP(i0 + 3, sv3, bc3, dd3, bc0);
    }
#undef SCAN1_STEP

    const int sb = ((b * NCHUNK + c) * NHEADS + h) * HEADDIM + p;
#pragma unroll
    for (int n = 0; n < DSTATE; n++) g_S[(size_t)sb * DSTATE + n] = hreg[n];
    if (p == 0) g_P[(b * NCHUNK + c) * NHEADS + h] = runD;
}

// ---------------- scan phase 2: deep-prefetch serial recurrence -------------
__global__ __launch_bounds__(1024) void scan_phase2()
{
    const int b = blockIdx.x >> 3, h = blockIdx.x & 7;
    const int tid = threadIdx.x;
    const size_t base0 = (size_t)((b * NCHUNK + 0) * NHEADS + h) * (HEADDIM * DSTATE) + tid;
    const size_t stride = (size_t)NHEADS * HEADDIM * DSTATE;
    const int pb = b * NCHUNK * NHEADS + h;

    float sbuf[8], pbuf[8];
#pragma unroll
    for (int j = 0; j < 8; j++) {
        sbuf[j] = g_S[base0 + (size_t)j * stride];
        pbuf[j] = g_P[pb + j * NHEADS];
    }
    float val = 0.f;
#pragma unroll 8
    for (int c = 0; c < NCHUNK; c++) {
        const int j = c & 7;
        g_hinit[base0 + (size_t)c * stride] = val;
        val = pbuf[j] * val + sbuf[j];
        if (c + 8 < NCHUNK) {
            sbuf[j] = g_S[base0 + (size_t)(c + 8) * stride];
            pbuf[j] = g_P[pb + (c + 8) * NHEADS];
        }
    }
}

// ---------------- scan finish: 4-deep const-idx prefetch + gate + RMSnorm ---
__global__ __launch_bounds__(512) void scan_finish(
    const float* __restrict__ Dp, const float* __restrict__ nw)
{
    const int c = blockIdx.x, b = blockIdx.y;
    const int tid = threadIdx.x;
    const int h = tid >> 6, p = tid & 63;
    const int warp = tid >> 5, lane = tid & 31;
    __shared__ float sBC[2][32];
    __shared__ float sred[2][16];

    float hreg[DSTATE];
    {
        const float* hi = &g_hinit[((size_t)((b * NCHUNK + c) * NHEADS + h) * HEADDIM + p) * DSTATE];
#pragma unroll
        for (int n = 0; n < DSTATE; n += 4) {
            float4 v = *(const float4*)&hi[n];
            hreg[n] = v.x; hreg[n+1] = v.y; hreg[n+2] = v.z; hreg[n+3] = v.w;
        }
    }
    const float Dpv = Dp[h];
    const float nwv = nw[tid];
    const int m0 = b * LL + c * QCHUNK;

    float sv0, sv1, sv2, sv3, zv0, zv1, zv2, zv3, bc0, bc1, bc2, bc3;
    float2 dd0, dd1, dd2, dd3;
    sv0 = g_xBCs[(size_t)(m0 + 0) * CONVDIM + tid];
    sv1 = g_xBCs[(size_t)(m0 + 1) * CONVDIM + tid];
    sv2 = g_xBCs[(size_t)(m0 + 2) * CONVDIM + tid];
    sv3 = g_xBCs[(size_t)(m0 + 3) * CONVDIM + tid];
    zv0 = g_zx[(size_t)(m0 + 0) * DPROJ + tid];
    zv1 = g_zx[(size_t)(m0 + 1) * DPROJ + tid];
    zv2 = g_zx[(size_t)(m0 + 2) * DPROJ + tid];
    zv3 = g_zx[(size_t)(m0 + 3) * DPROJ + tid];
    dd0 = *(const float2*)&g_dAdt[(size_t)((m0 + 0) * NHEADS + h) * 2];
    dd1 = *(const float2*)&g_dAdt[(size_t)((m0 + 1) * NHEADS + h) * 2];
    dd2 = *(const float2*)&g_dAdt[(size_t)((m0 + 2) * NHEADS + h) * 2];
    dd3 = *(const float2*)&g_dAdt[(size_t)((m0 + 3) * NHEADS + h) * 2];
    bc0 = bc1 = bc2 = bc3 = 0.f;
    if (tid < 32) {
        bc0 = g_xBCs[(size_t)(m0 + 0) * CONVDIM + DINNER + tid];
        bc1 = g_xBCs[(size_t)(m0 + 1) * CONVDIM + DINNER + tid];
        bc2 = g_xBCs[(size_t)(m0 + 2) * CONVDIM + DINNER + tid];
        bc3 = g_xBCs[(size_t)(m0 + 3) * CONVDIM + DINNER + tid];
        sBC[0][tid] = bc0;
    }
    __syncthreads();

#define SCANF_STEP(i, SV, ZV, BC, DD, BCN) { \
    const int m_ = m0 + (i); \
    const float da_ = DD.x; \
    const float xv_ = SV * DD.y; \
    const float svv_ = SV; \
    const float zvv_ = ZV; \
    if ((i) + 4 < QCHUNK) { \
        SV = g_xBCs[(size_t)(m_ + 4) * CONVDIM + tid]; \
        ZV = g_zx[(size_t)(m_ + 4) * DPROJ + tid]; \
        DD = *(const float2*)&g_dAdt[(size_t)((m_ + 4) * NHEADS + h) * 2]; \
        if (tid < 32) BC = g_xBCs[(size_t)(m_ + 4) * CONVDIM + DINNER + tid]; \
    } \
    float y0_ = 0.f, y1_ = 0.f; \
    _Pragma("unroll") \
    for (int n = 0; n < DSTATE; n += 2) { \
        hreg[n]     = da_ * hreg[n]     + xv_ * sBC[(i) & 1][n]; \
        hreg[n + 1] = da_ * hreg[n + 1] + xv_ * sBC[(i) & 1][n + 1]; \
        y0_ += hreg[n]     * sBC[(i) & 1][16 + n]; \
        y1_ += hreg[n + 1] * sBC[(i) & 1][16 + n + 1]; \
    } \
    const float y_ = y0_ + y1_ + Dpv * svv_; \
    const float yg_ = y_ * (zvv_ / (1.f + expf(-zvv_))); \
    float v_ = yg_ * yg_; \
    _Pragma("unroll") \
    for (int o = 16; o; o >>= 1) v_ += __shfl_xor_sync(0xffffffffu, v_, o); \
    if (lane == 0) sred[(i) & 1][warp] = v_; \
    if ((i) + 1 < QCHUNK && tid < 32) sBC[((i) + 1) & 1][tid] = BCN; \
    __syncthreads(); \
    float tot_ = 0.f; \
    _Pragma("unroll") \
    for (int ww = 0; ww < 16; ww++) tot_ += sred[(i) & 1][ww]; \
    const float rstd_ = rsqrtf(tot_ * (1.f / (float)DINNER) + 1e-5f); \
    g_ynorm[(size_t)m_ * DINNER + tid] = f2tf_f(yg_ * rstd_ * nwv); }

    for (int i0 = 0; i0 < QCHUNK; i0 += 4) {
        SCANF_STEP(i0 + 0, sv0, zv0, bc0, dd0, bc1);
        SCANF_STEP(i0 + 1, sv1, zv1, bc1, dd1, bc2);
        SCANF_STEP(i0 + 2, sv2, zv2, bc2, dd2, bc3);
        SCANF_STEP(i0 + 3, sv3, zv3, bc3, dd3, bc0);
    }
#undef SCANF_STEP
}

// ---------------- driver ---------------------------------------------------
extern "C" void kernel_launch(void* const* d_in, const int* in_sizes, int n_in,
                              void* d_out, int out_size)
{
    const float* x       = (const float*)d_in[0];
    const float* patch_w = (const float*)d_in[1];
    const float* patch_b = (const float*)d_in[2];
    const float* W_in    = (const float*)d_in[3];
    const float* conv_w  = (const float*)d_in[4];
    const float* conv_b  = (const float*)d_in[5];
    const float* dt_bias = (const float*)d_in[6];
    const float* A_log   = (const float*)d_in[7];
    const float* D_param = (const float*)d_in[8];
    const float* norm_w  = (const float*)d_in[9];
    const float* W_out   = (const float*)d_in[10];
    const float* unemb_w = (const float*)d_in[11];
    const float* unemb_b = (const float*)d_in[12];
    float* out = (float*)d_out;

    float *pWT, *pxs, *pzx, *pyn, *pWin, *pWout, *pWun, *pWcomb;
    cudaGetSymbolAddress((void**)&pWT,    g_patchWT);
    cudaGetSymbolAddress((void**)&pxs,    g_xs);
    cudaGetSymbolAddress((void**)&pzx,    g_zx);
    cudaGetSymbolAddress((void**)&pyn,    g_ynorm);
    cudaGetSymbolAddress((void**)&pWin,   g_Win_r);
    cudaGetSymbolAddress((void**)&pWout,  g_Wout_r);
    cudaGetSymbolAddress((void**)&pWun,   g_Wun_r);
    cudaGetSymbolAddress((void**)&pWcomb, g_Wcomb);

    cudaFuncSetAttribute(gemm_cp, cudaFuncAttributeMaxDynamicSharedMemorySize, GEMM_SMEM);
    cudaFuncSetAttribute(gemm_unembed, cudaFuncAttributeMaxDynamicSharedMemorySize, GEMM_SMEM);
    cudaFuncSetAttribute(patch_cp, cudaFuncAttributeMaxDynamicSharedMemorySize, GEMM_SMEM);
    cudaFuncSetAttribute(conv_tiled, cudaFuncAttributeMaxDynamicSharedMemorySize, CONV_SMEM);

    // weight prep (transpose + tf32 pre-rounding, single launch)
    prep_weights<<<(NW0 + NW1 + NW2 + NW3 + 255) / 256, 256>>>(patch_w, W_in, W_out, unemb_w);

    // combined output weight: Wcomb = W_out @ W_un  [512, 368]
    gemm_cp<<<dim3(3, DINNER / 128), 256, GEMM_SMEM>>>(
        pWout, pWun, pWcomb, DINNER, KPATCH, DM, 1);

    // patch embed (cp.async pipeline with fused im2col gather)
    patch_cp<<<dim3(2, MTOK / 128), 256, GEMM_SMEM>>>(x, pWT, pxs, patch_b);

    // in_proj
    gemm_cp<<<dim3((DPROJ + 127) / 128, MTOK / 128), 256, GEMM_SMEM>>>(
        pxs, pWin, pzx, MTOK, DPROJ, DM, 0);

    // conv + silu + dt/dA (tiled, fused)
    conv_tiled<<<MTOK / CTOK, 256, CONV_SMEM>>>(conv_w, conv_b, dt_bias, A_log);

    // chunked SSM scan + fused gate/RMSnorm
    scan_phase1<<<dim3(NCHUNK, BB), 512>>>();
    scan_phase2<<<BB * NHEADS, 1024>>>();
    scan_finish<<<dim3(NCHUNK, BB), 512>>>(D_param, norm_w);

    // combined out_proj+unembed GEMM + scatter + bias + residual
    gemm_unembed<<<dim3(3, MTOK / 128), 256, GEMM_SMEM>>>(pyn, pWcomb, x, unemb_b, out);
}